// round 1
// baseline (speedup 1.0000x reference)
#include <cuda_runtime.h>
#include <math.h>

// Problem constants
#define T_   32
#define B_   256
#define DIN_ 4196
#define H_   1024
#define C_   151

// Scratch (static __device__ — no allocations allowed)
__device__ float g_PI[(size_t)T_ * B_ * 6 * H_];   // [T*B, 6H] input projections
__device__ float g_PS[(size_t)B_ * 5 * H_];        // [B, 5H] recurrent projections (per step)
__device__ float g_HS[(size_t)T_ * B_ * H_];       // [T, B, H] hidden states (post-dropout)
__device__ float g_CB[2 * (size_t)B_ * H_];        // ping-pong cell state

// ---------------------------------------------------------------------------
// Tiled SGEMM computing C[M,N] = A[M,K] @ B[N,K]^T + bias[N]
// A row-major [M,K], B row-major [N,K]. K must be a multiple of 4.
// THREADS = (BM/TM)*(BN/TN) must be 256.
// ---------------------------------------------------------------------------
template<int BM, int BN, int TM, int TN>
__global__ void sgemm_bt(const float* __restrict__ A, const float* __restrict__ Bm,
                         const float* __restrict__ bias, float* __restrict__ C,
                         int M, int N, int K) {
    constexpr int BK = 16;
    constexpr int THREADS = (BM / TM) * (BN / TN);
    constexpr int PAD = 4;  // keep 16B alignment for float4 smem reads

    __shared__ float As[BK][BM + PAD];
    __shared__ float Bs[BK][BN + PAD];

    const int tid = threadIdx.x;
    const int m0 = blockIdx.y * BM;
    const int n0 = blockIdx.x * BN;

    const int tr = tid / (BN / TN);
    const int tc = tid % (BN / TN);

    float acc[TM][TN];
#pragma unroll
    for (int i = 0; i < TM; i++)
#pragma unroll
        for (int j = 0; j < TN; j++) acc[i][j] = 0.f;

    const int ktiles = (K + BK - 1) / BK;
    for (int kt = 0; kt < ktiles; ++kt) {
        const int k0 = kt * BK;

        // Load A tile [BM x BK] -> As[k][m]
#pragma unroll
        for (int i = tid; i < BM * BK / 4; i += THREADS) {
            const int row = i / (BK / 4);
            const int kq = (i % (BK / 4)) * 4;
            const int gm = m0 + row;
            const int gk = k0 + kq;
            float4 v = make_float4(0.f, 0.f, 0.f, 0.f);
            if (gm < M && gk < K)
                v = *reinterpret_cast<const float4*>(&A[(size_t)gm * K + gk]);
            As[kq + 0][row] = v.x;
            As[kq + 1][row] = v.y;
            As[kq + 2][row] = v.z;
            As[kq + 3][row] = v.w;
        }
        // Load B tile [BN x BK] -> Bs[k][n]
#pragma unroll
        for (int i = tid; i < BN * BK / 4; i += THREADS) {
            const int row = i / (BK / 4);
            const int kq = (i % (BK / 4)) * 4;
            const int gn = n0 + row;
            const int gk = k0 + kq;
            float4 v = make_float4(0.f, 0.f, 0.f, 0.f);
            if (gn < N && gk < K)
                v = *reinterpret_cast<const float4*>(&Bm[(size_t)gn * K + gk]);
            Bs[kq + 0][row] = v.x;
            Bs[kq + 1][row] = v.y;
            Bs[kq + 2][row] = v.z;
            Bs[kq + 3][row] = v.w;
        }
        __syncthreads();

#pragma unroll
        for (int kl = 0; kl < BK; ++kl) {
            float ra[TM], rb[TN];
#pragma unroll
            for (int i = 0; i < TM; i += 4) {
                float4 v = *reinterpret_cast<const float4*>(&As[kl][tr * TM + i]);
                ra[i + 0] = v.x; ra[i + 1] = v.y; ra[i + 2] = v.z; ra[i + 3] = v.w;
            }
#pragma unroll
            for (int j = 0; j < TN; j += 4) {
                float4 v = *reinterpret_cast<const float4*>(&Bs[kl][tc * TN + j]);
                rb[j + 0] = v.x; rb[j + 1] = v.y; rb[j + 2] = v.z; rb[j + 3] = v.w;
            }
#pragma unroll
            for (int i = 0; i < TM; i++)
#pragma unroll
                for (int j = 0; j < TN; j++)
                    acc[i][j] = fmaf(ra[i], rb[j], acc[i][j]);
        }
        __syncthreads();
    }

    // Epilogue with bias
#pragma unroll
    for (int i = 0; i < TM; i++) {
        const int gm = m0 + tr * TM + i;
        if (gm >= M) continue;
#pragma unroll
        for (int j = 0; j < TN; j++) {
            const int gn = n0 + tc * TN + j;
            if (gn < N) C[(size_t)gm * N + gn] = acc[i][j] + bias[gn];
        }
    }
}

// ---------------------------------------------------------------------------
// Fused LSTM-with-highway gates for one timestep.
// pi: [B, 6H] (this step's slice), ps: [B, 5H], c_in/c_out: [B*H],
// mask: [B*H], h_out: [B*H] (post-dropout hidden, also the carried state).
// ---------------------------------------------------------------------------
__device__ __forceinline__ float sigf(float x) { return 1.f / (1.f + expf(-x)); }

__global__ void gates_kernel(const float* __restrict__ pi, const float* __restrict__ ps,
                             const float* __restrict__ c_in, float* __restrict__ c_out,
                             const float* __restrict__ mask, float* __restrict__ h_out) {
    const int idx = blockIdx.x * blockDim.x + threadIdx.x;
    if (idx >= B_ * H_) return;
    const int b = idx / H_;
    const int j = idx % H_;
    const float* pib = pi + (size_t)b * 6 * H_;
    const float* psb = ps + (size_t)b * 5 * H_;

    const float i_g = sigf(pib[0 * H_ + j] + psb[0 * H_ + j]);
    const float f_g = sigf(pib[1 * H_ + j] + psb[1 * H_ + j]);
    const float m_i = tanhf(pib[2 * H_ + j] + psb[2 * H_ + j]);
    const float o_g = sigf(pib[3 * H_ + j] + psb[3 * H_ + j]);
    const float mem = i_g * m_i + f_g * c_in[idx];
    float out = o_g * tanhf(mem);
    const float hw = sigf(pib[4 * H_ + j] + psb[4 * H_ + j]);
    out = hw * out + (1.f - hw) * pib[5 * H_ + j];
    out *= mask[idx];
    c_out[idx] = mem;
    h_out[idx] = out;
}

// ---------------------------------------------------------------------------
extern "C" void kernel_launch(void* const* d_in, const int* in_sizes, int n_in,
                              void* d_out, int out_size) {
    const float* x       = (const float*)d_in[0];  // [T,B,DIN]
    const float* h0      = (const float*)d_in[1];  // [B,H]
    const float* c0      = (const float*)d_in[2];  // [B,H]
    const float* mask    = (const float*)d_in[3];  // [B,H]
    const float* W_in    = (const float*)d_in[4];  // [6H,DIN]
    const float* b_in    = (const float*)d_in[5];  // [6H]
    const float* W_state = (const float*)d_in[6];  // [5H,H]
    const float* b_state = (const float*)d_in[7];  // [5H]
    const float* W_out   = (const float*)d_in[8];  // [C,H]
    const float* b_out   = (const float*)d_in[9];  // [C]
    float* out = (float*)d_out;                    // [T,B,C]

    float *PI, *PS, *HS, *CB;
    cudaGetSymbolAddress((void**)&PI, g_PI);
    cudaGetSymbolAddress((void**)&PS, g_PS);
    cudaGetSymbolAddress((void**)&HS, g_HS);
    cudaGetSymbolAddress((void**)&CB, g_CB);

    const size_t BH = (size_t)B_ * H_;

    // 1) Input projection for all timesteps: PI[T*B, 6H] = x @ W_in^T + b_in
    {
        dim3 grid((6 * H_) / 128, (T_ * B_) / 128);
        sgemm_bt<128, 128, 8, 8><<<grid, 256>>>(x, W_in, b_in, PI,
                                                T_ * B_, 6 * H_, DIN_);
    }

    // 2) Sequential recurrence
    for (int t = 0; t < T_; ++t) {
        const float* hsrc = (t == 0) ? h0 : HS + (size_t)(t - 1) * BH;
        const float* csrc = (t == 0) ? c0 : CB + (size_t)((t - 1) & 1) * BH;
        float* cdst = CB + (size_t)(t & 1) * BH;
        float* hdst = HS + (size_t)t * BH;
        const float* pit = PI + (size_t)t * B_ * 6 * H_;

        dim3 grid((5 * H_) / 64, B_ / 64);
        sgemm_bt<64, 64, 4, 4><<<grid, 256>>>(hsrc, W_state, b_state, PS,
                                              B_, 5 * H_, H_);
        gates_kernel<<<(B_ * H_) / 256, 256>>>(pit, PS, csrc, cdst, mask, hdst);
    }

    // 3) Output projection: out[T*B, C] = HS @ W_out^T + b_out
    {
        dim3 grid((C_ + 63) / 64, (T_ * B_) / 64);
        sgemm_bt<64, 64, 4, 4><<<grid, 256>>>(HS, W_out, b_out, out,
                                              T_ * B_, C_, H_);
    }
}

// round 3
// speedup vs baseline: 3.1229x; 3.1229x over previous
#include <cuda_runtime.h>
#include <cuda_bf16.h>
#include <stdint.h>
#include <math.h>

// Problem constants
#define T_   32
#define B_   256
#define DIN_ 4196
#define H_   1024
#define C_   151

#define KP_IN   4224                 // DIN padded to mult of 64
#define KTOT_IN (3 * KP_IN)          // 12672 : [Ah|Al|Ah] / [Bh|Bh|Bl]
#define KTOT_ST (3 * H_)             // 3072

// ---------------------------------------------------------------------------
// Scratch (static __device__ — no allocations allowed)
// ---------------------------------------------------------------------------
__device__ __nv_bfloat16 g_A2 [(size_t)T_ * B_ * KTOT_IN];  // x split    [8192, 12672]
__device__ __nv_bfloat16 g_B2 [(size_t)6 * H_ * KTOT_IN];   // W_in split [6144, 12672]
__device__ __nv_bfloat16 g_Bst[(size_t)5 * H_ * KTOT_ST];   // W_state    [5120, 3072]
__device__ __nv_bfloat16 g_Ah [(size_t)B_ * KTOT_ST];       // h split    [256, 3072]
__device__ float g_PI[(size_t)T_ * B_ * 6 * H_];
__device__ float g_PS[(size_t)B_ * 5 * H_];
__device__ float g_HS[(size_t)T_ * B_ * H_];
__device__ float g_CB[2 * (size_t)B_ * H_];

// ---------------------------------------------------------------------------
// PTX helpers (baseline compute_103-safe: cp.async / ldmatrix / mma.sync only)
// ---------------------------------------------------------------------------
__device__ __forceinline__ uint32_t smem_u32(const void* p) {
    uint32_t a;
    asm("{ .reg .u64 t; cvta.to.shared.u64 t, %1; cvt.u32.u64 %0, t; }"
        : "=r"(a) : "l"(p));
    return a;
}
__device__ __forceinline__ void cp16(uint32_t d, const void* s) {
    asm volatile("cp.async.cg.shared.global [%0], [%1], 16;" :: "r"(d), "l"(s));
}
__device__ __forceinline__ void cp_commit() {
    asm volatile("cp.async.commit_group;" ::: "memory");
}
template <int N> __device__ __forceinline__ void cp_wait() {
    asm volatile("cp.async.wait_group %0;" :: "n"(N) : "memory");
}
__device__ __forceinline__ void ldsm4(uint32_t* r, uint32_t addr) {
    asm volatile("ldmatrix.sync.aligned.m8n8.x4.shared.b16 {%0,%1,%2,%3}, [%4];"
                 : "=r"(r[0]), "=r"(r[1]), "=r"(r[2]), "=r"(r[3]) : "r"(addr));
}
__device__ __forceinline__ void mma16816(float* c, const uint32_t* a, const uint32_t* b) {
    asm volatile(
        "mma.sync.aligned.m16n8k16.row.col.f32.bf16.bf16.f32 "
        "{%0,%1,%2,%3}, {%4,%5,%6,%7}, {%8,%9}, {%0,%1,%2,%3};"
        : "+f"(c[0]), "+f"(c[1]), "+f"(c[2]), "+f"(c[3])
        : "r"(a[0]), "r"(a[1]), "r"(a[2]), "r"(a[3]), "r"(b[0]), "r"(b[1]));
}

// SW64 swizzle for 64B rows (8-row x 64B atoms): conflict-free ldmatrix
#define SW64(o) ((o) ^ (((o) >> 3) & 0x30))

// ---------------------------------------------------------------------------
// bf16 tensor-core GEMM: C[M,N] = A[M,K]·B[N,K]^T + bias[N]
// A,B row-major bf16 (K-contig). M%BM==0, N%BN==0, K%32==0.
// 8 warps (256 thr). Warp tile WM x WN. 4-stage cp.async pipeline.
// ---------------------------------------------------------------------------
template<int BM, int BN, int WM, int WN>
__global__ void __launch_bounds__(256, 2)
mma_gemm(const __nv_bfloat16* __restrict__ A, const __nv_bfloat16* __restrict__ B,
         const float* __restrict__ bias, float* __restrict__ C,
         int M, int N, int K) {
    constexpr int STAGES = 4;
    constexpr int STG = (BM + BN) * 64;      // bytes per stage (BK=32 bf16 = 64B/row)
    constexpr int MW = BM / WM;              // warps along M
    constexpr int MT = WM / 16;              // m16 tiles per warp
    constexpr int NT = WN / 8;               // n8 tiles per warp
    constexpr int NP = WN / 16;              // n16 ldmatrix groups per warp

    extern __shared__ char smem[];
    const uint32_t sb = smem_u32(smem);
    const int tid = threadIdx.x;
    const int wid = tid >> 5;
    const int lane = tid & 31;
    const int wm = wid % MW;
    const int wn = wid / MW;
    const int l8 = lane & 7;
    const int sel = lane >> 3;
    const int m0 = blockIdx.y * BM;
    const int n0 = blockIdx.x * BN;
    const int KT = K / 32;

    auto load_stage = [&](int s, int kt) {
        const __nv_bfloat16* Ag = A + (size_t)m0 * K + kt * 32;
        const __nv_bfloat16* Bg = B + (size_t)n0 * K + kt * 32;
        const uint32_t stb = sb + s * STG;
#pragma unroll
        for (int i = tid; i < (BM + BN) * 4; i += 256) {
            if (i < BM * 4) {
                int row = i >> 2, c = i & 3;
                cp16(stb + SW64(row * 64 + c * 16),
                     Ag + (size_t)row * K + c * 8);
            } else {
                int j = i - BM * 4;
                int row = j >> 2, c = j & 3;
                cp16(stb + BM * 64 + SW64(row * 64 + c * 16),
                     Bg + (size_t)row * K + c * 8);
            }
        }
    };

    float acc[MT][NT][4];
#pragma unroll
    for (int i = 0; i < MT; i++)
#pragma unroll
        for (int j = 0; j < NT; j++)
#pragma unroll
            for (int v = 0; v < 4; v++) acc[i][j][v] = 0.f;

    // prologue: STAGES-1 committed groups (possibly empty)
#pragma unroll
    for (int s = 0; s < STAGES - 1; s++) {
        if (s < KT) load_stage(s, s);
        cp_commit();
    }

    for (int kt = 0; kt < KT; ++kt) {
        cp_wait<STAGES - 2>();
        __syncthreads();

        const int nk = kt + STAGES - 1;
        if (nk < KT) load_stage(nk % STAGES, nk);
        cp_commit();

        const uint32_t stb = sb + (kt % STAGES) * STG;
        const uint32_t stbB = stb + BM * 64;

#pragma unroll
        for (int ks = 0; ks < 2; ks++) {
            uint32_t ar[MT][4];
            uint32_t br[NP][4];
#pragma unroll
            for (int mt = 0; mt < MT; mt++) {
                int row = wm * WM + mt * 16 + l8 + (sel & 1) * 8;
                int ch = ks * 2 + (sel >> 1);
                ldsm4(ar[mt], stb + SW64(row * 64 + ch * 16));
            }
#pragma unroll
            for (int p = 0; p < NP; p++) {
                int row = wn * WN + p * 16 + l8 + (sel >> 1) * 8;
                int ch = ks * 2 + (sel & 1);
                ldsm4(br[p], stbB + SW64(row * 64 + ch * 16));
            }
#pragma unroll
            for (int mt = 0; mt < MT; mt++)
#pragma unroll
                for (int nt = 0; nt < NT; nt++)
                    mma16816(acc[mt][nt], ar[mt], &br[nt >> 1][(nt & 1) * 2]);
        }
    }

    // epilogue
    const int g4 = lane >> 2;
    const int t4 = lane & 3;
#pragma unroll
    for (int mt = 0; mt < MT; mt++) {
#pragma unroll
        for (int nt = 0; nt < NT; nt++) {
            const int r = m0 + wm * WM + mt * 16 + g4;
            const int col = n0 + wn * WN + nt * 8 + 2 * t4;
            const float b0 = bias[col], b1 = bias[col + 1];
            float2 v0 = make_float2(acc[mt][nt][0] + b0, acc[mt][nt][1] + b1);
            float2 v1 = make_float2(acc[mt][nt][2] + b0, acc[mt][nt][3] + b1);
            *reinterpret_cast<float2*>(&C[(size_t)r * N + col]) = v0;
            *reinterpret_cast<float2*>(&C[(size_t)(r + 8) * N + col]) = v1;
        }
    }
}

// ---------------------------------------------------------------------------
// Split-precision conversion: fp32 -> [hi|lo|hi] (A operand) or [hi|hi|lo] (B)
// ---------------------------------------------------------------------------
__global__ void split_A(const float* __restrict__ src, __nv_bfloat16* __restrict__ dst,
                        int K, int Kp, int total) {
    int idx = blockIdx.x * 256 + threadIdx.x;
    if (idx >= total) return;
    int r = idx / Kp, k = idx - r * Kp;
    float v = (k < K) ? src[(size_t)r * K + k] : 0.f;
    __nv_bfloat16 hi = __float2bfloat16(v);
    __nv_bfloat16 lo = __float2bfloat16(v - __bfloat162float(hi));
    __nv_bfloat16* row = dst + (size_t)r * 3 * Kp;
    row[k] = hi; row[Kp + k] = lo; row[2 * Kp + k] = hi;
}
__global__ void split_B(const float* __restrict__ src, __nv_bfloat16* __restrict__ dst,
                        int K, int Kp, int total) {
    int idx = blockIdx.x * 256 + threadIdx.x;
    if (idx >= total) return;
    int r = idx / Kp, k = idx - r * Kp;
    float v = (k < K) ? src[(size_t)r * K + k] : 0.f;
    __nv_bfloat16 hi = __float2bfloat16(v);
    __nv_bfloat16 lo = __float2bfloat16(v - __bfloat162float(hi));
    __nv_bfloat16* row = dst + (size_t)r * 3 * Kp;
    row[k] = hi; row[Kp + k] = hi; row[2 * Kp + k] = lo;
}

// ---------------------------------------------------------------------------
// Fused gates + recurrent-dropout + split-bf16 conversion of next h
// ---------------------------------------------------------------------------
__device__ __forceinline__ float sigf(float x) { return 1.f / (1.f + expf(-x)); }

__global__ void gates_kernel(const float* __restrict__ pi, const float* __restrict__ ps,
                             const float* __restrict__ c_in, float* __restrict__ c_out,
                             const float* __restrict__ mask, float* __restrict__ h_out,
                             __nv_bfloat16* __restrict__ Ah) {
    const int idx = blockIdx.x * blockDim.x + threadIdx.x;
    if (idx >= B_ * H_) return;
    const int b = idx / H_;
    const int j = idx - b * H_;
    const float* pib = pi + (size_t)b * 6 * H_;
    const float* psb = ps + (size_t)b * 5 * H_;

    const float i_g = sigf(pib[0 * H_ + j] + psb[0 * H_ + j]);
    const float f_g = sigf(pib[1 * H_ + j] + psb[1 * H_ + j]);
    const float m_i = tanhf(pib[2 * H_ + j] + psb[2 * H_ + j]);
    const float o_g = sigf(pib[3 * H_ + j] + psb[3 * H_ + j]);
    const float mem = i_g * m_i + f_g * c_in[idx];
    float out = o_g * tanhf(mem);
    const float hw = sigf(pib[4 * H_ + j] + psb[4 * H_ + j]);
    out = hw * out + (1.f - hw) * pib[5 * H_ + j];
    out *= mask[idx];
    c_out[idx] = mem;
    h_out[idx] = out;

    __nv_bfloat16 hi = __float2bfloat16(out);
    __nv_bfloat16 lo = __float2bfloat16(out - __bfloat162float(hi));
    __nv_bfloat16* row = Ah + (size_t)b * KTOT_ST;
    row[j] = hi; row[H_ + j] = lo; row[2 * H_ + j] = hi;
}

// ---------------------------------------------------------------------------
// fp32 SGEMM for the tiny output projection (N=151)
// ---------------------------------------------------------------------------
template<int BM, int BN, int TM, int TN>
__global__ void sgemm_bt(const float* __restrict__ A, const float* __restrict__ Bm,
                         const float* __restrict__ bias, float* __restrict__ C,
                         int M, int N, int K) {
    constexpr int BK = 16;
    constexpr int THREADS = (BM / TM) * (BN / TN);
    constexpr int PAD = 4;
    __shared__ float As[BK][BM + PAD];
    __shared__ float Bs[BK][BN + PAD];
    const int tid = threadIdx.x;
    const int m0 = blockIdx.y * BM;
    const int n0 = blockIdx.x * BN;
    const int tr = tid / (BN / TN);
    const int tc = tid % (BN / TN);
    float acc[TM][TN];
#pragma unroll
    for (int i = 0; i < TM; i++)
#pragma unroll
        for (int j = 0; j < TN; j++) acc[i][j] = 0.f;
    const int ktiles = (K + BK - 1) / BK;
    for (int kt = 0; kt < ktiles; ++kt) {
        const int k0 = kt * BK;
#pragma unroll
        for (int i = tid; i < BM * BK / 4; i += THREADS) {
            const int row = i / (BK / 4);
            const int kq = (i % (BK / 4)) * 4;
            float4 v = make_float4(0.f, 0.f, 0.f, 0.f);
            if (m0 + row < M && k0 + kq < K)
                v = *reinterpret_cast<const float4*>(&A[(size_t)(m0 + row) * K + k0 + kq]);
            As[kq + 0][row] = v.x; As[kq + 1][row] = v.y;
            As[kq + 2][row] = v.z; As[kq + 3][row] = v.w;
        }
#pragma unroll
        for (int i = tid; i < BN * BK / 4; i += THREADS) {
            const int row = i / (BK / 4);
            const int kq = (i % (BK / 4)) * 4;
            float4 v = make_float4(0.f, 0.f, 0.f, 0.f);
            if (n0 + row < N && k0 + kq < K)
                v = *reinterpret_cast<const float4*>(&Bm[(size_t)(n0 + row) * K + k0 + kq]);
            Bs[kq + 0][row] = v.x; Bs[kq + 1][row] = v.y;
            Bs[kq + 2][row] = v.z; Bs[kq + 3][row] = v.w;
        }
        __syncthreads();
#pragma unroll
        for (int kl = 0; kl < BK; ++kl) {
            float ra[TM], rb[TN];
#pragma unroll
            for (int i = 0; i < TM; i += 4) {
                float4 v = *reinterpret_cast<const float4*>(&As[kl][tr * TM + i]);
                ra[i] = v.x; ra[i + 1] = v.y; ra[i + 2] = v.z; ra[i + 3] = v.w;
            }
#pragma unroll
            for (int j = 0; j < TN; j += 4) {
                float4 v = *reinterpret_cast<const float4*>(&Bs[kl][tc * TN + j]);
                rb[j] = v.x; rb[j + 1] = v.y; rb[j + 2] = v.z; rb[j + 3] = v.w;
            }
#pragma unroll
            for (int i = 0; i < TM; i++)
#pragma unroll
                for (int j = 0; j < TN; j++)
                    acc[i][j] = fmaf(ra[i], rb[j], acc[i][j]);
        }
        __syncthreads();
    }
#pragma unroll
    for (int i = 0; i < TM; i++) {
        const int gm = m0 + tr * TM + i;
        if (gm >= M) continue;
#pragma unroll
        for (int j = 0; j < TN; j++) {
            const int gn = n0 + tc * TN + j;
            if (gn < N) C[(size_t)gm * N + gn] = acc[i][j] + bias[gn];
        }
    }
}

// ---------------------------------------------------------------------------
extern "C" void kernel_launch(void* const* d_in, const int* in_sizes, int n_in,
                              void* d_out, int out_size) {
    const float* x       = (const float*)d_in[0];
    const float* h0      = (const float*)d_in[1];
    const float* c0      = (const float*)d_in[2];
    const float* mask    = (const float*)d_in[3];
    const float* W_in    = (const float*)d_in[4];
    const float* b_in    = (const float*)d_in[5];
    const float* W_state = (const float*)d_in[6];
    const float* b_state = (const float*)d_in[7];
    const float* W_out   = (const float*)d_in[8];
    const float* b_out   = (const float*)d_in[9];
    float* out = (float*)d_out;

    __nv_bfloat16 *A2, *B2, *Bst, *Ah;
    float *PI, *PS, *HS, *CB;
    cudaGetSymbolAddress((void**)&A2, g_A2);
    cudaGetSymbolAddress((void**)&B2, g_B2);
    cudaGetSymbolAddress((void**)&Bst, g_Bst);
    cudaGetSymbolAddress((void**)&Ah, g_Ah);
    cudaGetSymbolAddress((void**)&PI, g_PI);
    cudaGetSymbolAddress((void**)&PS, g_PS);
    cudaGetSymbolAddress((void**)&HS, g_HS);
    cudaGetSymbolAddress((void**)&CB, g_CB);

    constexpr int SMEM_BIG = (128 + 128) * 64 * 4;   // 65536
    constexpr int SMEM_REC = (64 + 128) * 64 * 4;    // 49152
    cudaFuncSetAttribute(mma_gemm<128, 128, 32, 64>,
                         cudaFuncAttributeMaxDynamicSharedMemorySize, SMEM_BIG);
    cudaFuncSetAttribute(mma_gemm<64, 128, 32, 32>,
                         cudaFuncAttributeMaxDynamicSharedMemorySize, SMEM_REC);

    const size_t BH = (size_t)B_ * H_;

    // Split-precision conversions
    {
        int tot = T_ * B_ * KP_IN;
        split_A<<<(tot + 255) / 256, 256>>>(x, A2, DIN_, KP_IN, tot);
    }
    {
        int tot = 6 * H_ * KP_IN;
        split_B<<<(tot + 255) / 256, 256>>>(W_in, B2, DIN_, KP_IN, tot);
    }
    {
        int tot = 5 * H_ * H_;
        split_B<<<(tot + 255) / 256, 256>>>(W_state, Bst, H_, H_, tot);
    }
    {
        int tot = B_ * H_;
        split_A<<<(tot + 255) / 256, 256>>>(h0, Ah, H_, H_, tot);
    }

    // 1) Input projection: PI[8192, 6144] = x·W_in^T + b_in  (tensor cores)
    {
        dim3 grid((6 * H_) / 128, (T_ * B_) / 128);
        mma_gemm<128, 128, 32, 64><<<grid, 256, SMEM_BIG>>>(A2, B2, b_in, PI,
                                                            T_ * B_, 6 * H_, KTOT_IN);
    }

    // 2) Sequential recurrence
    for (int t = 0; t < T_; ++t) {
        const float* csrc = (t == 0) ? c0 : CB + (size_t)((t - 1) & 1) * BH;
        float* cdst = CB + (size_t)(t & 1) * BH;
        float* hdst = HS + (size_t)t * BH;
        const float* pit = PI + (size_t)t * B_ * 6 * H_;

        dim3 grid((5 * H_) / 128, B_ / 64);
        mma_gemm<64, 128, 32, 32><<<grid, 256, SMEM_REC>>>(Ah, Bst, b_state, PS,
                                                           B_, 5 * H_, KTOT_ST);
        gates_kernel<<<(B_ * H_) / 256, 256>>>(pit, PS, csrc, cdst, mask, hdst, Ah);
    }

    // 3) Output projection (fp32, tiny N)
    {
        dim3 grid((C_ + 63) / 64, (T_ * B_) / 64);
        sgemm_bt<64, 64, 4, 4><<<grid, 256>>>(HS, W_out, b_out, out,
                                              T_ * B_, C_, H_);
    }
}